// round 9
// baseline (speedup 1.0000x reference)
#include <cuda_runtime.h>
#include <cuda_bf16.h>
#include <cstdint>

// ============================================================================
// SSGP folded: f[n,i] = sum_{b<1024} cos(sim[n,b]+phi_b) * mat[b,i]
// via classic mma.sync.m16n8k16 bf16 (base ISA, works under compute_103).
// Split precision: x=xh+xl, q=qh+ql: sim = xh qh + xl qh + xh ql (drop lo*lo)
//                  c=ch+cl, m=mh+ml: f   = ch mh + cl mh + ch ml
// ============================================================================

__device__ float g_phi[1024];
__device__ __nv_bfloat16 g_qs[16][64][128];  // [chunk][b][ qh(64) | ql(64) ]
__device__ __nv_bfloat16 g_ms[16][64][128];  // [chunk][b][ mh(64) | ml(64) ]

// ---------------- prep (single kernel) ----------------
__global__ void ssgp_prep(const float* __restrict__ eps,
                          const float* __restrict__ lam,
                          const float* __restrict__ eta,
                          const float* __restrict__ w) {
    int idx = blockIdx.x * blockDim.x + threadIdx.x;  // 65536
    int b = idx >> 6, j = idx & 63;
    int ch = b >> 6, bp = b & 63;
    float S = w[b] + w[b + 1024];
    float C = w[2048 + b] - w[3072 + b];
    float R = sqrtf(S * S + C * C);
    if (j == 0) g_phi[b] = atan2f(S, C);

    float e2 = eta[0] * eta[0];
    float q = eps[b * 64 + j] / lam[j];
    __nv_bfloat16 qh = __float2bfloat16_rn(q);
    __nv_bfloat16 ql = __float2bfloat16_rn(q - __bfloat162float(qh));
    g_qs[ch][bp][j]      = qh;
    g_qs[ch][bp][64 + j] = ql;

    float m;
    if (j < 32) m = R * (eps[b * 64 + j + 32] / lam[j + 32]);
    else        m = -R * (eps[b * 64 + j - 32] / lam[j - 32] + e2 * q);
    __nv_bfloat16 mh = __float2bfloat16_rn(m);
    __nv_bfloat16 ml = __float2bfloat16_rn(m - __bfloat162float(mh));
    g_ms[ch][bp][j]      = mh;
    g_ms[ch][bp][64 + j] = ml;
}

// ---------------- asm helpers ----------------
__device__ __forceinline__ uint32_t smem_u32(const void* p) {
    uint32_t a;
    asm("{ .reg .u64 t; cvta.to.shared.u64 t, %1; cvt.u32.u64 %0, t; }" : "=r"(a) : "l"(p));
    return a;
}
__device__ __forceinline__ void mma16816(float* d, const uint32_t* a, const uint32_t* b) {
    asm volatile(
        "mma.sync.aligned.m16n8k16.row.col.f32.bf16.bf16.f32 "
        "{%0,%1,%2,%3}, {%4,%5,%6,%7}, {%8,%9}, {%0,%1,%2,%3};"
        : "+f"(d[0]), "+f"(d[1]), "+f"(d[2]), "+f"(d[3])
        : "r"(a[0]), "r"(a[1]), "r"(a[2]), "r"(a[3]), "r"(b[0]), "r"(b[1]));
}
__device__ __forceinline__ void ldsm_x4(uint32_t* r, uint32_t addr) {
    asm volatile("ldmatrix.sync.aligned.m8n8.x4.shared.b16 {%0,%1,%2,%3}, [%4];"
                 : "=r"(r[0]), "=r"(r[1]), "=r"(r[2]), "=r"(r[3]) : "r"(addr));
}
__device__ __forceinline__ void ldsm_x4t(uint32_t* r, uint32_t addr) {
    asm volatile("ldmatrix.sync.aligned.m8n8.x4.trans.shared.b16 {%0,%1,%2,%3}, [%4];"
                 : "=r"(r[0]), "=r"(r[1]), "=r"(r[2]), "=r"(r[3]) : "r"(addr));
}
__device__ __forceinline__ void cpa16(uint32_t s, const void* g) {
    asm volatile("cp.async.cg.shared.global [%0], [%1], 16;" :: "r"(s), "l"(g));
}
__device__ __forceinline__ uint32_t pack_bf2(float lo, float hi) {
    __nv_bfloat162 v(__float2bfloat16_rn(lo), __float2bfloat16_rn(hi));
    return *(uint32_t*)&v;
}

// ---------------- smem layout ----------------
#define ROWB 272                  // 128 bf16 + 16B pad
#define SX_OFF 0                  // x tile: 64 rows x ROWB
#define Q_OFF  17408              // 4 bufs (half, dbuf)
#define M_OFF  (17408 + 4*17408)  // 87040, 4 bufs
#define PHI_OFF (87040 + 4*17408) // 156672, 1024 f32
#define SMEM_BYTES (156672 + 4096)
#define QBUF(h,d) (Q_OFF + ((h)*2+(d))*17408)
#define MBUF(h,d) (M_OFF + ((h)*2+(d))*17408)

__device__ __forceinline__ void pf_chunk(uint32_t sb, int half, int gc, int d, int t128) {
    uint32_t qdst = sb + QBUF(half, d);
    uint32_t mdst = sb + MBUF(half, d);
    const char* qsrc = (const char*)g_qs[gc];
    const char* msrc = (const char*)g_ms[gc];
#pragma unroll
    for (int r = 0; r < 8; r++) {
        int e = t128 + r * 128;                 // 1024 x 16B units
        uint32_t off = (uint32_t)(e >> 4) * ROWB + (uint32_t)(e & 15) * 16;
        cpa16(qdst + off, qsrc + e * 16);
        cpa16(mdst + off, msrc + e * 16);
    }
}

// ---------------- main ----------------
__global__ void __launch_bounds__(256, 1)
ssgp_hmma(const float* __restrict__ x, float* __restrict__ out) {
    extern __shared__ char smem[];
    const uint32_t sb = smem_u32(smem);
    const int tid = threadIdx.x, lane = tid & 31, w = tid >> 5;
    const int half = w >> 2, mrow = (w & 3) * 16;
    const int t128 = tid & 127;
    const int row0 = blockIdx.x * 64;
    const int c0 = half * 8;

    // prefetch phi + first two chunks for this half
    cpa16(sb + PHI_OFF + tid * 16, (const char*)g_phi + tid * 16);
    pf_chunk(sb, half, c0 + 0, 0, t128);
    asm volatile("cp.async.commit_group;");
    pf_chunk(sb, half, c0 + 1, 1, t128);
    asm volatile("cp.async.commit_group;");

    // stage x tile: 64 rows x [xh(64)|xl(64)] bf16, row stride ROWB
#pragma unroll
    for (int k = 0; k < 4; k++) {
        int e = tid + k * 256;                 // 1024 float4s
        int row = e >> 4, c4 = e & 15;
        float4 v = *(const float4*)&x[(row0 + row) * 64 + c4 * 4];
        float vh[4] = {v.x, v.y, v.z, v.w};
        uint32_t hp[2], lp[2];
#pragma unroll
        for (int p = 0; p < 2; p++) {
            float a = vh[2 * p], b = vh[2 * p + 1];
            float ah = __bfloat162float(__float2bfloat16_rn(a));
            float bh = __bfloat162float(__float2bfloat16_rn(b));
            hp[p] = pack_bf2(a, b);
            lp[p] = pack_bf2(a - ah, b - bh);
        }
        char* rp = smem + SX_OFF + row * ROWB;
        *(uint2*)(rp + c4 * 8)       = make_uint2(hp[0], hp[1]);
        *(uint2*)(rp + 128 + c4 * 8) = make_uint2(lp[0], lp[1]);
    }
    __syncthreads();

    // load persistent x A-fragments: [hi/lo][jb][4]
    uint32_t xa[2][4][4];
#pragma unroll
    for (int s = 0; s < 2; s++)
#pragma unroll
        for (int jb = 0; jb < 4; jb++) {
            uint32_t addr = sb + SX_OFF + (uint32_t)(mrow + (lane & 15)) * ROWB
                          + (uint32_t)(s * 64 + jb * 16 + ((lane >> 4) & 1) * 8) * 2;
            ldsm_x4(xa[s][jb], addr);
        }

    float f[8][4];
#pragma unroll
    for (int it = 0; it < 8; it++)
#pragma unroll
        for (int r = 0; r < 4; r++) f[it][r] = 0.f;

    const float* sphi = (const float*)(smem + PHI_OFF);

    for (int cc = 0; cc < 8; ++cc) {
        asm volatile("cp.async.wait_group 1;" ::: "memory");
        asm volatile("bar.sync %0, 128;" :: "r"(1 + half) : "memory");
        const uint32_t qb = sb + QBUF(half, cc & 1);
        const uint32_t mb = sb + MBUF(half, cc & 1);
        const int gc = c0 + cc;

        // ---- GEMM1: sim[16 x 64] = x . q^T over K=192 split ----
        // nt processed in pairs with jb-interchange -> 2 independent chains
        float s[8][4];
#pragma unroll
        for (int nt2 = 0; nt2 < 4; nt2++) {
            uint32_t bh[2][4][2], bl[2][4][2];
#pragma unroll
            for (int p = 0; p < 2; p++) {
                int nt = nt2 * 2 + p;
                uint32_t base = qb + (uint32_t)(nt * 8 + (lane & 7)) * ROWB
                              + (uint32_t)((lane >> 3) * 8) * 2;
                uint32_t r[4];
                ldsm_x4(r, base);                 // k 0..31 hi
                bh[p][0][0] = r[0]; bh[p][0][1] = r[1];
                bh[p][1][0] = r[2]; bh[p][1][1] = r[3];
                ldsm_x4(r, base + 32 * 2);        // k 32..63 hi
                bh[p][2][0] = r[0]; bh[p][2][1] = r[1];
                bh[p][3][0] = r[2]; bh[p][3][1] = r[3];
                ldsm_x4(r, base + 64 * 2);        // k 0..31 lo
                bl[p][0][0] = r[0]; bl[p][0][1] = r[1];
                bl[p][1][0] = r[2]; bl[p][1][1] = r[3];
                ldsm_x4(r, base + 96 * 2);        // k 32..63 lo
                bl[p][2][0] = r[0]; bl[p][2][1] = r[1];
                bl[p][3][0] = r[2]; bl[p][3][1] = r[3];
            }
            int n0 = nt2 * 2, n1 = nt2 * 2 + 1;
#pragma unroll
            for (int r4 = 0; r4 < 4; r4++) { s[n0][r4] = 0.f; s[n1][r4] = 0.f; }
#pragma unroll
            for (int jb = 0; jb < 4; jb++) {
                mma16816(s[n0], xa[0][jb], bh[0][jb]);
                mma16816(s[n1], xa[0][jb], bh[1][jb]);
            }
#pragma unroll
            for (int jb = 0; jb < 4; jb++) {
                mma16816(s[n0], xa[1][jb], bh[0][jb]);
                mma16816(s[n1], xa[1][jb], bh[1][jb]);
            }
#pragma unroll
            for (int jb = 0; jb < 4; jb++) {
                mma16816(s[n0], xa[0][jb], bl[0][jb]);
                mma16816(s[n1], xa[0][jb], bl[1][jb]);
            }
        }

        // ---- epilogue: cos(sim+phi) -> bf16 split -> A2 frags ----
        uint32_t ah[4][4], al[4][4];
#pragma unroll
        for (int nt = 0; nt < 8; nt++) {
            int cb = nt * 8 + (lane & 3) * 2;
            float p0 = sphi[gc * 64 + cb], p1 = sphi[gc * 64 + cb + 1];
            float v0 = __cosf(s[nt][0] + p0);
            float v1 = __cosf(s[nt][1] + p1);
            float v2 = __cosf(s[nt][2] + p0);
            float v3 = __cosf(s[nt][3] + p1);
            float h0 = __bfloat162float(__float2bfloat16_rn(v0));
            float h1 = __bfloat162float(__float2bfloat16_rn(v1));
            float h2 = __bfloat162float(__float2bfloat16_rn(v2));
            float h3 = __bfloat162float(__float2bfloat16_rn(v3));
            int t = nt >> 1, o = (nt & 1) * 2;
            ah[t][o]     = pack_bf2(v0, v1);
            ah[t][o + 1] = pack_bf2(v2, v3);
            al[t][o]     = pack_bf2(v0 - h0, v1 - h1);
            al[t][o + 1] = pack_bf2(v2 - h2, v3 - h3);
        }

        // ---- GEMM2: f += coeff . mat over K=64, split (8 indep chains) ----
#pragma unroll
        for (int it = 0; it < 8; it++) {
            uint32_t bh[4][2], bl[4][2], r[4];
            uint32_t base = mb + (uint32_t)lane * ROWB + (uint32_t)(it * 8) * 2;
            ldsm_x4t(r, base);                    // k(b) 0..31 hi
            bh[0][0] = r[0]; bh[0][1] = r[1]; bh[1][0] = r[2]; bh[1][1] = r[3];
            ldsm_x4t(r, base + 32u * ROWB);       // k(b) 32..63 hi
            bh[2][0] = r[0]; bh[2][1] = r[1]; bh[3][0] = r[2]; bh[3][1] = r[3];
            ldsm_x4t(r, base + 128);              // lo
            bl[0][0] = r[0]; bl[0][1] = r[1]; bl[1][0] = r[2]; bl[1][1] = r[3];
            ldsm_x4t(r, base + 32u * ROWB + 128);
            bl[2][0] = r[0]; bl[2][1] = r[1]; bl[3][0] = r[2]; bl[3][1] = r[3];
#pragma unroll
            for (int kb = 0; kb < 4; kb++) mma16816(f[it], ah[kb], bh[kb]);
#pragma unroll
            for (int kb = 0; kb < 4; kb++) mma16816(f[it], al[kb], bh[kb]);
#pragma unroll
            for (int kb = 0; kb < 4; kb++) mma16816(f[it], ah[kb], bl[kb]);
        }

        asm volatile("bar.sync %0, 128;" :: "r"(1 + half) : "memory");
        if (cc + 2 < 8) pf_chunk(sb, half, c0 + cc + 2, cc & 1, t128);
        asm volatile("cp.async.commit_group;");
    }

    // ---- write per-half partials to smem (reuse q bufs), combine ----
    float* sf = (float*)(smem + QBUF(half, 0));   // 64 x 68 f32 = 17408B
    {
        int r = mrow + lane / 4;
        int cbase = (lane & 3) * 2;
#pragma unroll
        for (int it = 0; it < 8; it++) {
            int col = it * 8 + cbase;
            *(float2*)&sf[r * 68 + col]       = make_float2(f[it][0], f[it][1]);
            *(float2*)&sf[(r + 8) * 68 + col] = make_float2(f[it][2], f[it][3]);
        }
    }
    __syncthreads();
    const float* sf0 = (const float*)(smem + QBUF(0, 0));
    const float* sf1 = (const float*)(smem + QBUF(1, 0));
#pragma unroll
    for (int k = 0; k < 4; k++) {
        int e = tid + k * 256;
        int row = e >> 4, c4 = (e & 15) * 4;
        float4 a = *(const float4*)&sf0[row * 68 + c4];
        float4 b = *(const float4*)&sf1[row * 68 + c4];
        float4 o;
        o.x = a.x + b.x; o.y = a.y + b.y; o.z = a.z + b.z; o.w = a.w + b.w;
        *(float4*)&out[(row0 + row) * 64 + c4] = o;
    }
}

extern "C" void kernel_launch(void* const* d_in, const int* in_sizes, int n_in,
                              void* d_out, int out_size) {
    // inputs: 0=t(1), 1=x(8192*64), 2=epsilon(2048*64), 3=lam(64), 4=eta(1), 5=w(4096)
    const float* x   = (const float*)d_in[1];
    const float* eps = (const float*)d_in[2];
    const float* lam = (const float*)d_in[3];
    const float* eta = (const float*)d_in[4];
    const float* w   = (const float*)d_in[5];
    float* out = (float*)d_out;

    ssgp_prep<<<256, 256>>>(eps, lam, eta, w);

    cudaFuncSetAttribute(ssgp_hmma, cudaFuncAttributeMaxDynamicSharedMemorySize,
                         SMEM_BYTES);
    ssgp_hmma<<<128, 256, SMEM_BYTES>>>(x, out);
}